// round 6
// baseline (speedup 1.0000x reference)
#include <cuda_runtime.h>

#define TPB 128           // threads per block; each thread does 2 points
typedef unsigned long long ull;

// ---- shared-memory layout (floats). All weights/biases stored DUPLICATED:
// element w occupies two consecutive floats (w, w) so one 64-bit load feeds
// a packed fma.rn.f32x2. Hidden matrices transposed to [out_j][in_k dup].
namespace off {
constexpr int W1d  = 0;     // [2][60]   (in k)(out j dup)
constexpr int B1d  = 120;   // [60]
constexpr int W2d  = 180;   // [30][60]  (out j)(in k dup)
constexpr int B2d  = 1980;  // [60]
constexpr int W3d  = 2040;  // [30][60]
constexpr int B3d  = 3840;  // [60]
constexpr int W4d  = 3900;  // [8][60]
constexpr int B4d  = 4380;  // [16]
constexpr int P1d  = 4396;  // [2][32]   (in k)(out j dup, 15 used)
constexpr int PB1d = 4460;  // [32]
constexpr int P2d  = 4492;  // [15][32]  (out j)(in k dup, 16 lanes, lane15=0)
constexpr int PB2d = 4972;  // [32]
constexpr int P3d  = 5004;  // [15][32]
constexpr int PB3d = 5484;  // [32]
constexpr int P4d  = 5516;  // [4][32]
constexpr int PB4d = 5644;  // [8]
constexpr int IMV  = 5652;  // [2]
constexpr int LMB  = 5654;  // [1]
constexpr int TOTAL = 5656; // ~22.6 KB
}

// ---- packed f32x2 helpers ----
__device__ __forceinline__ ull pk2(float lo, float hi) {
    ull r; asm("mov.b64 %0, {%1, %2};" : "=l"(r) : "f"(lo), "f"(hi)); return r;
}
__device__ __forceinline__ void upk2(ull v, float& lo, float& hi) {
    asm("mov.b64 {%0, %1}, %2;" : "=f"(lo), "=f"(hi) : "l"(v));
}
__device__ __forceinline__ ull ffma2(ull a, ull b, ull c) {
    ull d; asm("fma.rn.f32x2 %0, %1, %2, %3;" : "=l"(d) : "l"(a), "l"(b), "l"(c)); return d;
}
__device__ __forceinline__ ull fadd2(ull a, ull b) {
    ull d; asm("add.rn.f32x2 %0, %1, %2;" : "=l"(d) : "l"(a), "l"(b)); return d;
}

// tanh via EX2 + fast divide (~1e-7 abs err)
__device__ __forceinline__ float fast_tanhf(float v) {
    float a = fabsf(v);
    float e = __expf(-2.0f * a);
    float r = __fdividef(1.0f - e, 1.0f + e);
    return copysignf(r, v);
}
__device__ __forceinline__ ull tanh2(ull v) {
    float lo, hi; upk2(v, lo, hi);
    return pk2(fast_tanhf(lo), fast_tanhf(hi));
}

// Branchless half-angle: (c,s) on unit circle -> sin(th/2), cos(th/2).
__device__ __forceinline__ void half_angle(float c, float s, float& sh, float& ch) {
    float root = sqrtf(0.5f * (1.0f + fabsf(c)));
    float q    = __fdividef(s, 2.0f * root);
    bool pos   = (c >= 0.0f);
    sh = pos ? q    : copysignf(root, s);
    ch = pos ? root : fabsf(q);
}

// geometry per point
__device__ __forceinline__ void geom(float x0, float x1, float im0, float im1,
                                     float& bx, float& by, float& r, float& yita) {
    const float d0 = x0 - im0, d1 = x1 - im1;
    r = sqrtf(fmaf(d0, d0, d1 * d1));
    const float ir = __fdividef(1.0f, r);
    bx = d0 * ir; by = d1 * ir;
    const float t  = fminf(fmaxf(fmaf(2.5f, r, -1.25f), 0.0f), 1.0f);
    const float t3 = t * t * t;
    yita = fmaf(fmaf(fmaf(-6.0f, t, 15.0f), t, -10.0f), t3, 1.0f);
}

// epilogue per point
__device__ __forceinline__ float combine(float x0, float x1, float bx, float by,
                                         float r, float yita,
                                         const float* w, const float* ph, float lm) {
    // vphi at x: r^k sin(k th), k = .5, 1, 1.5
    const float rr  = sqrtf(fmaf(x0, x0, x1 * x1));
    const float irr = __fdividef(1.0f, rr);
    const float cc  = x0 * irr, ss = x1 * irr;
    float sh, ch; half_angle(cc, ss, sh, ch);
    const float sqr = sqrtf(rr);
    const float vp0 = sqr * sh;
    const float vp1 = rr * ss;
    const float vp2 = (rr * sqr) * fmaf(ss, ch, cc * sh);
    // vphi_sig at unit vector (bx, by)
    float shb, chb; half_angle(bx, by, shb, chb);
    const float vs2 = fmaf(by, chb, bx * shb);

    const float rp = w[0] + yita * w[4]
                   + fmaf(yita, w[5], w[1]) * vp0
                   + fmaf(yita, w[6], w[2]) * vp1
                   + fmaf(yita, w[7], w[3]) * vp2;
    const float sv = ph[0] + ph[1] * shb + ph[2] * by + ph[3] * vs2;
    const float rl = (lm == 0.5f) ? sqrtf(r) : __powf(r, lm);
    return fmaf(sv * yita, rl, rp);
}

__global__ void __launch_bounds__(TPB)
mlp_interior_kernel(
    const float* __restrict__ x,
    const float* __restrict__ imv,
    const float* __restrict__ lmbd,
    const float* __restrict__ Ww1, const float* __restrict__ bw1,
    const float* __restrict__ Ww2, const float* __restrict__ bw2,
    const float* __restrict__ Ww3, const float* __restrict__ bw3,
    const float* __restrict__ Ww4, const float* __restrict__ bw4,
    const float* __restrict__ Wp1, const float* __restrict__ bp1,
    const float* __restrict__ Wp2, const float* __restrict__ bp2,
    const float* __restrict__ Wp3, const float* __restrict__ bp3,
    const float* __restrict__ Wp4, const float* __restrict__ bp4,
    float* __restrict__ out, int N)
{
    __shared__ float S[off::TOTAL];
    const int tid = threadIdx.x;

    for (int k = tid; k < off::TOTAL; k += TPB) S[k] = 0.0f;
    __syncthreads();

    // duplicated fills: element v -> slots (2e, 2e+1)
    for (int t = tid; t < 60; t += TPB) {            // Ww1 [2][30]
        int k = t / 30, j = t % 30; float v = Ww1[t];
        S[off::W1d + k * 60 + 2 * j] = v; S[off::W1d + k * 60 + 2 * j + 1] = v;
    }
    for (int t = tid; t < 30; t += TPB) { float v = bw1[t]; S[off::B1d + 2*t] = v; S[off::B1d + 2*t + 1] = v; }
    for (int t = tid; t < 900; t += TPB) {           // Ww2 [30][30] -> [j][k dup]
        int k = t / 30, j = t % 30; float v = Ww2[t];
        S[off::W2d + j * 60 + 2 * k] = v; S[off::W2d + j * 60 + 2 * k + 1] = v;
    }
    for (int t = tid; t < 30; t += TPB) { float v = bw2[t]; S[off::B2d + 2*t] = v; S[off::B2d + 2*t + 1] = v; }
    for (int t = tid; t < 900; t += TPB) {           // Ww3
        int k = t / 30, j = t % 30; float v = Ww3[t];
        S[off::W3d + j * 60 + 2 * k] = v; S[off::W3d + j * 60 + 2 * k + 1] = v;
    }
    for (int t = tid; t < 30; t += TPB) { float v = bw3[t]; S[off::B3d + 2*t] = v; S[off::B3d + 2*t + 1] = v; }
    for (int t = tid; t < 240; t += TPB) {           // Ww4 [30][8]
        int k = t / 8, j = t % 8; float v = Ww4[t];
        S[off::W4d + j * 60 + 2 * k] = v; S[off::W4d + j * 60 + 2 * k + 1] = v;
    }
    for (int t = tid; t < 8; t += TPB) { float v = bw4[t]; S[off::B4d + 2*t] = v; S[off::B4d + 2*t + 1] = v; }
    for (int t = tid; t < 30; t += TPB) {            // Wp1 [2][15]
        int k = t / 15, j = t % 15; float v = Wp1[t];
        S[off::P1d + k * 32 + 2 * j] = v; S[off::P1d + k * 32 + 2 * j + 1] = v;
    }
    for (int t = tid; t < 15; t += TPB) { float v = bp1[t]; S[off::PB1d + 2*t] = v; S[off::PB1d + 2*t + 1] = v; }
    for (int t = tid; t < 225; t += TPB) {           // Wp2 [15][15]
        int k = t / 15, j = t % 15; float v = Wp2[t];
        S[off::P2d + j * 32 + 2 * k] = v; S[off::P2d + j * 32 + 2 * k + 1] = v;
    }
    for (int t = tid; t < 15; t += TPB) { float v = bp2[t]; S[off::PB2d + 2*t] = v; S[off::PB2d + 2*t + 1] = v; }
    for (int t = tid; t < 225; t += TPB) {           // Wp3
        int k = t / 15, j = t % 15; float v = Wp3[t];
        S[off::P3d + j * 32 + 2 * k] = v; S[off::P3d + j * 32 + 2 * k + 1] = v;
    }
    for (int t = tid; t < 15; t += TPB) { float v = bp3[t]; S[off::PB3d + 2*t] = v; S[off::PB3d + 2*t + 1] = v; }
    for (int t = tid; t < 60; t += TPB) {            // Wp4 [15][4]
        int k = t / 4, j = t % 4; float v = Wp4[t];
        S[off::P4d + j * 32 + 2 * k] = v; S[off::P4d + j * 32 + 2 * k + 1] = v;
    }
    for (int t = tid; t < 4; t += TPB) { float v = bp4[t]; S[off::PB4d + 2*t] = v; S[off::PB4d + 2*t + 1] = v; }
    if (tid == 0) {
        S[off::IMV]     = imv[0];
        S[off::IMV + 1] = imv[1];
        S[off::LMB]     = lmbd[0];
    }
    __syncthreads();

    const int i0 = blockIdx.x * (2 * TPB) + tid;   // point A
    const int i1 = i0 + TPB;                       // point B
    if (i0 >= N) return;
    const bool hasB = (i1 < N);

    const float2 xa = reinterpret_cast<const float2*>(x)[i0];
    const float2 xb = hasB ? reinterpret_cast<const float2*>(x)[i1] : xa;

    const ull X0 = pk2(xa.x, xb.x);
    const ull X1 = pk2(xa.y, xb.y);

    // ---------- w MLP: 2 -> 30 -> 30 -> 30 -> 8, packed over 2 points ----------
    ull h2[30], g2[30];
    {
        const ull* w0 = reinterpret_cast<const ull*>(&S[off::W1d]);
        const ull* w1 = reinterpret_cast<const ull*>(&S[off::W1d + 60]);
        const ull* bb = reinterpret_cast<const ull*>(&S[off::B1d]);
        #pragma unroll
        for (int j = 0; j < 30; ++j)
            h2[j] = tanh2(ffma2(X0, w0[j], ffma2(X1, w1[j], bb[j])));
    }
    #pragma unroll
    for (int j = 0; j < 30; ++j) {
        const ulonglong2* row = reinterpret_cast<const ulonglong2*>(&S[off::W2d + j * 60]);
        ull a0 = *reinterpret_cast<const ull*>(&S[off::B2d + 2 * j]);
        ull a1 = 0, a2 = 0, a3 = 0;
        #pragma unroll
        for (int c = 0; c < 15; ++c) {
            ulonglong2 wv = row[c];
            if (c & 1) { a2 = ffma2(h2[2*c], wv.x, a2); a3 = ffma2(h2[2*c+1], wv.y, a3); }
            else       { a0 = ffma2(h2[2*c], wv.x, a0); a1 = ffma2(h2[2*c+1], wv.y, a1); }
        }
        g2[j] = tanh2(fadd2(fadd2(a0, a2), fadd2(a1, a3)));
    }
    #pragma unroll
    for (int j = 0; j < 30; ++j) {
        const ulonglong2* row = reinterpret_cast<const ulonglong2*>(&S[off::W3d + j * 60]);
        ull a0 = *reinterpret_cast<const ull*>(&S[off::B3d + 2 * j]);
        ull a1 = 0, a2 = 0, a3 = 0;
        #pragma unroll
        for (int c = 0; c < 15; ++c) {
            ulonglong2 wv = row[c];
            if (c & 1) { a2 = ffma2(g2[2*c], wv.x, a2); a3 = ffma2(g2[2*c+1], wv.y, a3); }
            else       { a0 = ffma2(g2[2*c], wv.x, a0); a1 = ffma2(g2[2*c+1], wv.y, a1); }
        }
        h2[j] = tanh2(fadd2(fadd2(a0, a2), fadd2(a1, a3)));
    }
    float wA[8], wB[8];
    #pragma unroll
    for (int j = 0; j < 8; ++j) {
        const ulonglong2* row = reinterpret_cast<const ulonglong2*>(&S[off::W4d + j * 60]);
        ull a0 = *reinterpret_cast<const ull*>(&S[off::B4d + 2 * j]);
        ull a1 = 0, a2 = 0, a3 = 0;
        #pragma unroll
        for (int c = 0; c < 15; ++c) {
            ulonglong2 wv = row[c];
            if (c & 1) { a2 = ffma2(h2[2*c], wv.x, a2); a3 = ffma2(h2[2*c+1], wv.y, a3); }
            else       { a0 = ffma2(h2[2*c], wv.x, a0); a1 = ffma2(h2[2*c+1], wv.y, a1); }
        }
        upk2(fadd2(fadd2(a0, a2), fadd2(a1, a3)), wA[j], wB[j]);
    }

    // ---------- geometry (scalar per point) ----------
    const float im0 = S[off::IMV], im1 = S[off::IMV + 1];
    float bxA, byA, rA, yiA; geom(xa.x, xa.y, im0, im1, bxA, byA, rA, yiA);
    float bxB, byB, rB, yiB; geom(xb.x, xb.y, im0, im1, bxB, byB, rB, yiB);

    const ull BX = pk2(bxA, bxB);
    const ull BY = pk2(byA, byB);

    // ---------- phi MLP: 2 -> 15 -> 15 -> 15 -> 4, packed ----------
    ull p2[16], q2[16];
    {
        const ull* w0 = reinterpret_cast<const ull*>(&S[off::P1d]);
        const ull* w1 = reinterpret_cast<const ull*>(&S[off::P1d + 32]);
        const ull* bb = reinterpret_cast<const ull*>(&S[off::PB1d]);
        #pragma unroll
        for (int j = 0; j < 15; ++j)
            p2[j] = tanh2(ffma2(BX, w0[j], ffma2(BY, w1[j], bb[j])));
        p2[15] = 0;
    }
    #pragma unroll
    for (int j = 0; j < 15; ++j) {
        const ulonglong2* row = reinterpret_cast<const ulonglong2*>(&S[off::P2d + j * 32]);
        ull a0 = *reinterpret_cast<const ull*>(&S[off::PB2d + 2 * j]);
        ull a1 = 0, a2 = 0, a3 = 0;
        #pragma unroll
        for (int c = 0; c < 8; ++c) {        // k = 2c, 2c+1; lane 15 weight & act are 0
            ulonglong2 wv = row[c];
            if (c & 1) { a2 = ffma2(p2[2*c], wv.x, a2); a3 = ffma2(p2[2*c+1], wv.y, a3); }
            else       { a0 = ffma2(p2[2*c], wv.x, a0); a1 = ffma2(p2[2*c+1], wv.y, a1); }
        }
        q2[j] = tanh2(fadd2(fadd2(a0, a2), fadd2(a1, a3)));
    }
    q2[15] = 0;
    #pragma unroll
    for (int j = 0; j < 15; ++j) {
        const ulonglong2* row = reinterpret_cast<const ulonglong2*>(&S[off::P3d + j * 32]);
        ull a0 = *reinterpret_cast<const ull*>(&S[off::PB3d + 2 * j]);
        ull a1 = 0, a2 = 0, a3 = 0;
        #pragma unroll
        for (int c = 0; c < 8; ++c) {
            ulonglong2 wv = row[c];
            if (c & 1) { a2 = ffma2(q2[2*c], wv.x, a2); a3 = ffma2(q2[2*c+1], wv.y, a3); }
            else       { a0 = ffma2(q2[2*c], wv.x, a0); a1 = ffma2(q2[2*c+1], wv.y, a1); }
        }
        p2[j] = tanh2(fadd2(fadd2(a0, a2), fadd2(a1, a3)));
    }
    p2[15] = 0;
    float phA[4], phB[4];
    #pragma unroll
    for (int j = 0; j < 4; ++j) {
        const ulonglong2* row = reinterpret_cast<const ulonglong2*>(&S[off::P4d + j * 32]);
        ull a0 = *reinterpret_cast<const ull*>(&S[off::PB4d + 2 * j]);
        ull a1 = 0, a2 = 0, a3 = 0;
        #pragma unroll
        for (int c = 0; c < 8; ++c) {
            ulonglong2 wv = row[c];
            if (c & 1) { a2 = ffma2(p2[2*c], wv.x, a2); a3 = ffma2(p2[2*c+1], wv.y, a3); }
            else       { a0 = ffma2(p2[2*c], wv.x, a0); a1 = ffma2(p2[2*c+1], wv.y, a1); }
        }
        upk2(fadd2(fadd2(a0, a2), fadd2(a1, a3)), phA[j], phB[j]);
    }

    // ---------- epilogue ----------
    const float lm = S[off::LMB];
    out[i0] = combine(xa.x, xa.y, bxA, byA, rA, yiA, wA, phA, lm);
    if (hasB)
        out[i1] = combine(xb.x, xb.y, bxB, byB, rB, yiB, wB, phB, lm);
}

extern "C" void kernel_launch(void* const* d_in, const int* in_sizes, int n_in,
                              void* d_out, int out_size) {
    const float* x    = (const float*)d_in[0];
    const float* imv  = (const float*)d_in[1];
    const float* lmbd = (const float*)d_in[2];
    const float* Ww1  = (const float*)d_in[3];
    const float* bw1  = (const float*)d_in[4];
    const float* Ww2  = (const float*)d_in[5];
    const float* bw2  = (const float*)d_in[6];
    const float* Ww3  = (const float*)d_in[7];
    const float* bw3  = (const float*)d_in[8];
    const float* Ww4  = (const float*)d_in[9];
    const float* bw4  = (const float*)d_in[10];
    const float* Wp1  = (const float*)d_in[11];
    const float* bp1  = (const float*)d_in[12];
    const float* Wp2  = (const float*)d_in[13];
    const float* bp2  = (const float*)d_in[14];
    const float* Wp3  = (const float*)d_in[15];
    const float* bp3  = (const float*)d_in[16];
    const float* Wp4  = (const float*)d_in[17];
    const float* bp4  = (const float*)d_in[18];
    float* out = (float*)d_out;

    const int N = out_size;
    const int blocks = (N + 2 * TPB - 1) / (2 * TPB);
    mlp_interior_kernel<<<blocks, TPB>>>(
        x, imv, lmbd,
        Ww1, bw1, Ww2, bw2, Ww3, bw3, Ww4, bw4,
        Wp1, bp1, Wp2, bp2, Wp3, bp3, Wp4, bp4,
        out, N);
}